// round 16
// baseline (speedup 1.0000x reference)
#include <cuda_runtime.h>
#include <cuda_bf16.h>
#include <cstdint>

#define B_ROWS 16384
#define DDIM   1024
#define CCLS   1000

#define BM 128
#define BN 128
#define BK 64
#define KITERS 16
#define STAGES 3
#define STAGE_BYTES 32768          // A 16KB + B 16KB
#define SM_MISC (STAGES * STAGE_BYTES)          // 98304
#define SMEM_TOTAL (SM_MISC + 128*4*4 + 128*4)  // + partial[128][4] + labsm[128]

// Scratch (allocation-free rule)
__device__ __nv_bfloat16 g_x[(size_t)B_ROWS * DDIM];
__device__ __nv_bfloat16 g_p[(size_t)1024 * DDIM];
__device__ float g_rowsum[B_ROWS];
__device__ float g_gold[B_ROWS];

__device__ __forceinline__ uint32_t smem_u32(const void* p) {
    uint32_t a;
    asm("{ .reg .u64 t; cvta.to.shared.u64 t, %1; cvt.u32.u64 %0, t; }" : "=r"(a) : "l"(p));
    return a;
}
__device__ __forceinline__ void cpa16(uint32_t daddr, const void* src) {
    asm volatile("cp.async.cg.shared.global [%0], [%1], 16;" :: "r"(daddr), "l"(src));
}
__device__ __forceinline__ void ldsm4(uint32_t* r, uint32_t addr) {
    asm volatile("ldmatrix.sync.aligned.m8n8.x4.shared.b16 {%0,%1,%2,%3}, [%4];"
                 : "=r"(r[0]), "=r"(r[1]), "=r"(r[2]), "=r"(r[3]) : "r"(addr));
}
__device__ __forceinline__ void mma16816(float* c, const uint32_t* a, uint32_t b0, uint32_t b1) {
    asm volatile(
        "mma.sync.aligned.m16n8k16.row.col.f32.bf16.bf16.f32 "
        "{%0,%1,%2,%3},{%4,%5,%6,%7},{%8,%9},{%0,%1,%2,%3};\n"
        : "+f"(c[0]), "+f"(c[1]), "+f"(c[2]), "+f"(c[3])
        : "r"(a[0]), "r"(a[1]), "r"(a[2]), "r"(a[3]), "r"(b0), "r"(b1));
}

// ---------------------------------------------------------------------------
// Prep: blocks [0, 8192) normalize 2 hs rows each (threads 0-127 / 128-255);
// blocks [8192, 8704) convert 2 prototype rows each. Block 8192 zeroes out[0].
// Each thread handles 8 floats (2 x float4) -> MLP=2, one sync per block.
// ---------------------------------------------------------------------------
__global__ __launch_bounds__(256) void prep_kernel(const float* __restrict__ hs,
                                                    const float* __restrict__ P,
                                                    float* __restrict__ out) {
    __shared__ float wsum[8];     // 4 warp-partials per row half
    const int half = threadIdx.x >> 7;          // 0 or 1 -> which row
    const int ht   = threadIdx.x & 127;         // thread within half
    if (blockIdx.x < B_ROWS / 2) {
        const int row = blockIdx.x * 2 + half;
        if (ht == 0) g_rowsum[row] = 0.0f;
        const float4* src = (const float4*)(hs + (size_t)row * DDIM);
        float4 v0 = src[ht];
        float4 v1 = src[ht + 128];
        float ss = v0.x * v0.x + v0.y * v0.y + v0.z * v0.z + v0.w * v0.w
                 + v1.x * v1.x + v1.y * v1.y + v1.z * v1.z + v1.w * v1.w;
        #pragma unroll
        for (int o = 16; o; o >>= 1) ss += __shfl_xor_sync(0xffffffffu, ss, o);
        const int w = threadIdx.x >> 5;         // 0..7 (4 warps per half)
        if ((threadIdx.x & 31) == 0) wsum[w] = ss;
        __syncthreads();
        float tot = wsum[half * 4] + wsum[half * 4 + 1]
                  + wsum[half * 4 + 2] + wsum[half * 4 + 3];
        float s = rsqrtf(tot);
        __nv_bfloat162* dst0 = (__nv_bfloat162*)(g_x + (size_t)row * DDIM + ht * 4);
        dst0[0] = __floats2bfloat162_rn(v0.x * s, v0.y * s);
        dst0[1] = __floats2bfloat162_rn(v0.z * s, v0.w * s);
        __nv_bfloat162* dst1 = (__nv_bfloat162*)(g_x + (size_t)row * DDIM + (ht + 128) * 4);
        dst1[0] = __floats2bfloat162_rn(v1.x * s, v1.y * s);
        dst1[1] = __floats2bfloat162_rn(v1.z * s, v1.w * s);
    } else {
        const int prow = (blockIdx.x - B_ROWS / 2) * 2 + half;   // 0..1023
        if (blockIdx.x == B_ROWS / 2 && threadIdx.x == 0) out[0] = 0.0f;
        if (prow < CCLS) {
            const float4* src = (const float4*)(P + (size_t)prow * DDIM);
            float4 v0 = src[ht];
            float4 v1 = src[ht + 128];
            __nv_bfloat162* dst0 = (__nv_bfloat162*)(g_p + (size_t)prow * DDIM + ht * 4);
            dst0[0] = __floats2bfloat162_rn(v0.x, v0.y);
            dst0[1] = __floats2bfloat162_rn(v0.z, v0.w);
            __nv_bfloat162* dst1 = (__nv_bfloat162*)(g_p + (size_t)prow * DDIM + (ht + 128) * 4);
            dst1[0] = __floats2bfloat162_rn(v1.x, v1.y);
            dst1[1] = __floats2bfloat162_rn(v1.z, v1.w);
        } else {
            *(uint2*)(g_p + (size_t)prow * DDIM + ht * 4) = make_uint2(0u, 0u);
            *(uint2*)(g_p + (size_t)prow * DDIM + (ht + 128) * 4) = make_uint2(0u, 0u);
        }
    }
}

// ---------------------------------------------------------------------------
extern __shared__ char smem_g[];

__device__ __forceinline__ void load_stage(uint32_t base, int stage, int tid,
                                            const __nv_bfloat16* gA,
                                            const __nv_bfloat16* gB) {
    const int kk = stage * BK;
    #pragma unroll
    for (int i = 0; i < 4; i++) {
        int idx = tid + i * 256;
        int r = idx >> 3, s = idx & 7;
        uint32_t off = (uint32_t)(r * 128 + ((s ^ (r & 7)) << 4));
        cpa16(base + off,         gA + (size_t)r * DDIM + kk + s * 8);
        cpa16(base + 16384 + off, gB + (size_t)r * DDIM + kk + s * 8);
    }
}

__global__ __launch_bounds__(256, 2) void gemm_ce(const long long* __restrict__ labels) {
    uint32_t sb = smem_u32(smem_g);
    const int tid = threadIdx.x;
    const int wid = tid >> 5, lane = tid & 31;
    const int row0 = blockIdx.x * BM;
    const int n0   = blockIdx.y * BN;

    float* partial = (float*)(smem_g + SM_MISC);   // [128][4]
    int*   labsm   = (int*)(partial + 128 * 4);    // [128]

    const __nv_bfloat16* gA = g_x + (size_t)row0 * DDIM;
    const __nv_bfloat16* gB = g_p + (size_t)n0 * DDIM;

    load_stage(sb, 0, tid, gA, gB);
    asm volatile("cp.async.commit_group;");
    load_stage(sb + STAGE_BYTES, 1, tid, gA, gB);
    asm volatile("cp.async.commit_group;");
    if (tid < 128) labsm[tid] = (int)labels[row0 + tid];

    const int warpM = wid >> 2;      // 0..1  (64 rows each)
    const int warpN = wid & 3;       // 0..3  (32 cols each)
    const int x7 = lane & 7;
    const int laneRowA = (lane & 7) + ((lane >> 3) & 1) * 8;
    const int kHalfA   = lane >> 4;
    const int laneRowB = (lane & 7) + (lane >> 4) * 8;
    const int kHalfB   = (lane >> 3) & 1;

    uint32_t rowOffA[4], rowOffB[2];
    #pragma unroll
    for (int mt = 0; mt < 4; mt++)
        rowOffA[mt] = (uint32_t)((warpM * 64 + mt * 16 + laneRowA) * 128);
    #pragma unroll
    for (int np = 0; np < 2; np++)
        rowOffB[np] = (uint32_t)((warpN * 32 + np * 16 + laneRowB) * 128) + 16384;

    float acc[4][4][4];
    #pragma unroll
    for (int mt = 0; mt < 4; mt++)
        #pragma unroll
        for (int nt = 0; nt < 4; nt++)
            #pragma unroll
            for (int j = 0; j < 4; j++) acc[mt][nt][j] = 0.f;

    uint32_t baseCur = sb;
    uint32_t baseNxt = sb + 2 * STAGE_BYTES;

    for (int t = 0; t < KITERS; t++) {
        if (t + 2 < KITERS) {
            asm volatile("cp.async.wait_group 1;" ::: "memory");
        } else {
            asm volatile("cp.async.wait_group 0;" ::: "memory");
        }
        __syncthreads();

        if (t + 2 < KITERS) {
            load_stage(baseNxt, t + 2, tid, gA, gB);
            asm volatile("cp.async.commit_group;");
        }

        const uint32_t sbase = baseCur;
        #pragma unroll
        for (int ks = 0; ks < 4; ks++) {
            uint32_t a[4][4], b[2][4];
            const uint32_t xsA = (uint32_t)(((ks * 2 + kHalfA) ^ x7) << 4);
            #pragma unroll
            for (int mt = 0; mt < 4; mt++)
                ldsm4(a[mt], sbase + rowOffA[mt] + xsA);
            const uint32_t xsB = (uint32_t)(((ks * 2 + kHalfB) ^ x7) << 4);
            #pragma unroll
            for (int np = 0; np < 2; np++)
                ldsm4(b[np], sbase + rowOffB[np] + xsB);
            #pragma unroll
            for (int mt = 0; mt < 4; mt++)
                #pragma unroll
                for (int nt = 0; nt < 4; nt++)
                    mma16816(acc[mt][nt], a[mt], b[nt >> 1][(nt & 1) * 2],
                             b[nt >> 1][(nt & 1) * 2 + 1]);
        }

        uint32_t bc = baseCur + STAGE_BYTES;
        baseCur = (bc >= sb + 3 * STAGE_BYTES) ? sb : bc;
        uint32_t bn = baseNxt + STAGE_BYTES;
        baseNxt = (bn >= sb + 3 * STAGE_BYTES) ? sb : bn;
    }

    // ---- epilogue: masked sum-exp + gold capture ----
    #pragma unroll
    for (int mt = 0; mt < 4; mt++) {
        #pragma unroll
        for (int rh = 0; rh < 2; rh++) {
            int row = warpM * 64 + mt * 16 + rh * 8 + (lane >> 2);
            int labr = labsm[row];
            float se = 0.f;
            #pragma unroll
            for (int nt = 0; nt < 4; nt++) {
                int c0 = n0 + warpN * 32 + nt * 8 + (lane & 3) * 2;
                float v0 = acc[mt][nt][rh * 2 + 0];
                float v1 = acc[mt][nt][rh * 2 + 1];
                if (c0     < CCLS) se += __expf(v0);
                if (c0 + 1 < CCLS) se += __expf(v1);
                if (c0     == labr) g_gold[row0 + row] = v0;
                if (c0 + 1 == labr) g_gold[row0 + row] = v1;
            }
            se += __shfl_xor_sync(0xffffffffu, se, 1);
            se += __shfl_xor_sync(0xffffffffu, se, 2);
            if ((lane & 3) == 0) partial[row * 4 + warpN] = se;
        }
    }
    __syncthreads();
    if (tid < 128) {
        float t = partial[tid * 4] + partial[tid * 4 + 1]
                + partial[tid * 4 + 2] + partial[tid * 4 + 3];
        atomicAdd(&g_rowsum[row0 + tid], t);
    }
}

// ---------------------------------------------------------------------------
__global__ __launch_bounds__(256) void finalize(float* __restrict__ out) {
    int r = blockIdx.x * 256 + threadIdx.x;
    float loss = __logf(g_rowsum[r]) - g_gold[r];
    #pragma unroll
    for (int o = 16; o; o >>= 1) loss += __shfl_xor_sync(0xffffffffu, loss, o);
    __shared__ float ws[8];
    int w = threadIdx.x >> 5, l = threadIdx.x & 31;
    if (l == 0) ws[w] = loss;
    __syncthreads();
    if (threadIdx.x == 0) {
        float tot = 0.f;
        #pragma unroll
        for (int i = 0; i < 8; i++) tot += ws[i];
        atomicAdd(out, tot * (1.0f / (float)B_ROWS));
    }
}

// ---------------------------------------------------------------------------
extern "C" void kernel_launch(void* const* d_in, const int* in_sizes, int n_in,
                              void* d_out, int out_size) {
    const float*     hs = (const float*)d_in[0];
    const float*     pm = (const float*)d_in[1];
    const long long* lb = (const long long*)d_in[2];
    float* out = (float*)d_out;

    cudaFuncSetAttribute(gemm_ce, cudaFuncAttributeMaxDynamicSharedMemorySize, SMEM_TOTAL);

    prep_kernel<<<B_ROWS / 2 + 512, 256>>>(hs, pm, out);
    dim3 grid(B_ROWS / BM, 8);
    gemm_ce<<<grid, 256, SMEM_TOTAL>>>(lb);
    finalize<<<B_ROWS / 256, 256>>>(out);
}

// round 17
// speedup vs baseline: 1.0168x; 1.0168x over previous
#include <cuda_runtime.h>
#include <cuda_bf16.h>
#include <cstdint>

#define B_ROWS 16384
#define DDIM   1024
#define CCLS   1000

#define BM 128
#define BN 128
#define BK 64
#define KITERS 16
#define STAGES 3
#define STAGE_BYTES 32768          // A 16KB + B 16KB
#define SM_MISC (STAGES * STAGE_BYTES)          // 98304
#define SMEM_TOTAL (SM_MISC + 128*4*4 + 128*4)  // + partial[128][4] + labsm[128]

// Scratch (allocation-free rule)
__device__ __nv_bfloat16 g_x[(size_t)B_ROWS * DDIM];
__device__ __nv_bfloat16 g_p[(size_t)1024 * DDIM];
__device__ float g_rowsum[B_ROWS];
__device__ float g_gold[B_ROWS];

__device__ __forceinline__ uint32_t smem_u32(const void* p) {
    uint32_t a;
    asm("{ .reg .u64 t; cvta.to.shared.u64 t, %1; cvt.u32.u64 %0, t; }" : "=r"(a) : "l"(p));
    return a;
}
__device__ __forceinline__ void cpa16(uint32_t daddr, const void* src) {
    asm volatile("cp.async.cg.shared.global [%0], [%1], 16;" :: "r"(daddr), "l"(src));
}
__device__ __forceinline__ void ldsm4(uint32_t* r, uint32_t addr) {
    asm volatile("ldmatrix.sync.aligned.m8n8.x4.shared.b16 {%0,%1,%2,%3}, [%4];"
                 : "=r"(r[0]), "=r"(r[1]), "=r"(r[2]), "=r"(r[3]) : "r"(addr));
}
__device__ __forceinline__ void mma16816(float* c, const uint32_t* a, uint32_t b0, uint32_t b1) {
    asm volatile(
        "mma.sync.aligned.m16n8k16.row.col.f32.bf16.bf16.f32 "
        "{%0,%1,%2,%3},{%4,%5,%6,%7},{%8,%9},{%0,%1,%2,%3};\n"
        : "+f"(c[0]), "+f"(c[1]), "+f"(c[2]), "+f"(c[3])
        : "r"(a[0]), "r"(a[1]), "r"(a[2]), "r"(a[3]), "r"(b0), "r"(b1));
}

// ---------------------------------------------------------------------------
// Prep: 4 rows per 256-thread block (64 threads per row, 4 float4 per thread).
// Blocks [0, 4096): normalize hs rows. Blocks [4096, 4352): convert P (4 rows
// each, zero-padded to 1024). Block 4096 zeroes out[0].
// ---------------------------------------------------------------------------
__global__ __launch_bounds__(256) void prep_kernel(const float* __restrict__ hs,
                                                    const float* __restrict__ P,
                                                    float* __restrict__ out) {
    __shared__ float wsum[8];                   // per-warp partials (2 warps/row)
    const int rloc = threadIdx.x >> 6;          // 0..3: row within block
    const int ht   = threadIdx.x & 63;          // thread within row
    const int w    = threadIdx.x >> 5;          // warp 0..7
    if (blockIdx.x < B_ROWS / 4) {
        const int row = blockIdx.x * 4 + rloc;
        if (ht == 0) g_rowsum[row] = 0.0f;
        const float4* src = (const float4*)(hs + (size_t)row * DDIM);
        float4 v0 = src[ht];
        float4 v1 = src[ht + 64];
        float4 v2 = src[ht + 128];
        float4 v3 = src[ht + 192];
        float ss = v0.x * v0.x + v0.y * v0.y + v0.z * v0.z + v0.w * v0.w
                 + v1.x * v1.x + v1.y * v1.y + v1.z * v1.z + v1.w * v1.w
                 + v2.x * v2.x + v2.y * v2.y + v2.z * v2.z + v2.w * v2.w
                 + v3.x * v3.x + v3.y * v3.y + v3.z * v3.z + v3.w * v3.w;
        #pragma unroll
        for (int o = 16; o; o >>= 1) ss += __shfl_xor_sync(0xffffffffu, ss, o);
        if ((threadIdx.x & 31) == 0) wsum[w] = ss;
        __syncthreads();
        float s = rsqrtf(wsum[rloc * 2] + wsum[rloc * 2 + 1]);
        __nv_bfloat16* base = g_x + (size_t)row * DDIM;
        __nv_bfloat162* d0 = (__nv_bfloat162*)(base + ht * 4);
        d0[0] = __floats2bfloat162_rn(v0.x * s, v0.y * s);
        d0[1] = __floats2bfloat162_rn(v0.z * s, v0.w * s);
        __nv_bfloat162* d1 = (__nv_bfloat162*)(base + (ht + 64) * 4);
        d1[0] = __floats2bfloat162_rn(v1.x * s, v1.y * s);
        d1[1] = __floats2bfloat162_rn(v1.z * s, v1.w * s);
        __nv_bfloat162* d2 = (__nv_bfloat162*)(base + (ht + 128) * 4);
        d2[0] = __floats2bfloat162_rn(v2.x * s, v2.y * s);
        d2[1] = __floats2bfloat162_rn(v2.z * s, v2.w * s);
        __nv_bfloat162* d3 = (__nv_bfloat162*)(base + (ht + 192) * 4);
        d3[0] = __floats2bfloat162_rn(v3.x * s, v3.y * s);
        d3[1] = __floats2bfloat162_rn(v3.z * s, v3.w * s);
    } else {
        const int prow = (blockIdx.x - B_ROWS / 4) * 4 + rloc;   // 0..1023
        if (blockIdx.x == B_ROWS / 4 && threadIdx.x == 0) out[0] = 0.0f;
        __nv_bfloat16* base = g_p + (size_t)prow * DDIM;
        if (prow < CCLS) {
            const float4* src = (const float4*)(P + (size_t)prow * DDIM);
            float4 v0 = src[ht];
            float4 v1 = src[ht + 64];
            float4 v2 = src[ht + 128];
            float4 v3 = src[ht + 192];
            __nv_bfloat162* d0 = (__nv_bfloat162*)(base + ht * 4);
            d0[0] = __floats2bfloat162_rn(v0.x, v0.y);
            d0[1] = __floats2bfloat162_rn(v0.z, v0.w);
            __nv_bfloat162* d1 = (__nv_bfloat162*)(base + (ht + 64) * 4);
            d1[0] = __floats2bfloat162_rn(v1.x, v1.y);
            d1[1] = __floats2bfloat162_rn(v1.z, v1.w);
            __nv_bfloat162* d2 = (__nv_bfloat162*)(base + (ht + 128) * 4);
            d2[0] = __floats2bfloat162_rn(v2.x, v2.y);
            d2[1] = __floats2bfloat162_rn(v2.z, v2.w);
            __nv_bfloat162* d3 = (__nv_bfloat162*)(base + (ht + 192) * 4);
            d3[0] = __floats2bfloat162_rn(v3.x, v3.y);
            d3[1] = __floats2bfloat162_rn(v3.z, v3.w);
        } else {
            *(uint2*)(base + ht * 4)         = make_uint2(0u, 0u);
            *(uint2*)(base + (ht + 64) * 4)  = make_uint2(0u, 0u);
            *(uint2*)(base + (ht + 128) * 4) = make_uint2(0u, 0u);
            *(uint2*)(base + (ht + 192) * 4) = make_uint2(0u, 0u);
        }
    }
}

// ---------------------------------------------------------------------------
extern __shared__ char smem_g[];

__device__ __forceinline__ void load_stage(uint32_t base, int stage, int tid,
                                            const __nv_bfloat16* gA,
                                            const __nv_bfloat16* gB) {
    const int kk = stage * BK;
    #pragma unroll
    for (int i = 0; i < 4; i++) {
        int idx = tid + i * 256;
        int r = idx >> 3, s = idx & 7;
        uint32_t off = (uint32_t)(r * 128 + ((s ^ (r & 7)) << 4));
        cpa16(base + off,         gA + (size_t)r * DDIM + kk + s * 8);
        cpa16(base + 16384 + off, gB + (size_t)r * DDIM + kk + s * 8);
    }
}

__global__ __launch_bounds__(256, 2) void gemm_ce(const long long* __restrict__ labels) {
    uint32_t sb = smem_u32(smem_g);
    const int tid = threadIdx.x;
    const int wid = tid >> 5, lane = tid & 31;
    const int row0 = blockIdx.x * BM;
    const int n0   = blockIdx.y * BN;

    float* partial = (float*)(smem_g + SM_MISC);   // [128][4]
    int*   labsm   = (int*)(partial + 128 * 4);    // [128]

    const __nv_bfloat16* gA = g_x + (size_t)row0 * DDIM;
    const __nv_bfloat16* gB = g_p + (size_t)n0 * DDIM;

    load_stage(sb, 0, tid, gA, gB);
    asm volatile("cp.async.commit_group;");
    load_stage(sb + STAGE_BYTES, 1, tid, gA, gB);
    asm volatile("cp.async.commit_group;");
    if (tid < 128) labsm[tid] = (int)labels[row0 + tid];

    const int warpM = wid >> 2;      // 0..1  (64 rows each)
    const int warpN = wid & 3;       // 0..3  (32 cols each)
    const int x7 = lane & 7;
    const int laneRowA = (lane & 7) + ((lane >> 3) & 1) * 8;
    const int kHalfA   = lane >> 4;
    const int laneRowB = (lane & 7) + (lane >> 4) * 8;
    const int kHalfB   = (lane >> 3) & 1;

    uint32_t rowOffA[4], rowOffB[2];
    #pragma unroll
    for (int mt = 0; mt < 4; mt++)
        rowOffA[mt] = (uint32_t)((warpM * 64 + mt * 16 + laneRowA) * 128);
    #pragma unroll
    for (int np = 0; np < 2; np++)
        rowOffB[np] = (uint32_t)((warpN * 32 + np * 16 + laneRowB) * 128) + 16384;

    float acc[4][4][4];
    #pragma unroll
    for (int mt = 0; mt < 4; mt++)
        #pragma unroll
        for (int nt = 0; nt < 4; nt++)
            #pragma unroll
            for (int j = 0; j < 4; j++) acc[mt][nt][j] = 0.f;

    uint32_t baseCur = sb;
    uint32_t baseNxt = sb + 2 * STAGE_BYTES;

    for (int t = 0; t < KITERS; t++) {
        if (t + 2 < KITERS) {
            asm volatile("cp.async.wait_group 1;" ::: "memory");
        } else {
            asm volatile("cp.async.wait_group 0;" ::: "memory");
        }
        __syncthreads();

        if (t + 2 < KITERS) {
            load_stage(baseNxt, t + 2, tid, gA, gB);
            asm volatile("cp.async.commit_group;");
        }

        const uint32_t sbase = baseCur;
        #pragma unroll
        for (int ks = 0; ks < 4; ks++) {
            uint32_t a[4][4], b[2][4];
            const uint32_t xsA = (uint32_t)(((ks * 2 + kHalfA) ^ x7) << 4);
            #pragma unroll
            for (int mt = 0; mt < 4; mt++)
                ldsm4(a[mt], sbase + rowOffA[mt] + xsA);
            const uint32_t xsB = (uint32_t)(((ks * 2 + kHalfB) ^ x7) << 4);
            #pragma unroll
            for (int np = 0; np < 2; np++)
                ldsm4(b[np], sbase + rowOffB[np] + xsB);
            #pragma unroll
            for (int mt = 0; mt < 4; mt++)
                #pragma unroll
                for (int nt = 0; nt < 4; nt++)
                    mma16816(acc[mt][nt], a[mt], b[nt >> 1][(nt & 1) * 2],
                             b[nt >> 1][(nt & 1) * 2 + 1]);
        }

        uint32_t bc = baseCur + STAGE_BYTES;
        baseCur = (bc >= sb + 3 * STAGE_BYTES) ? sb : bc;
        uint32_t bn = baseNxt + STAGE_BYTES;
        baseNxt = (bn >= sb + 3 * STAGE_BYTES) ? sb : bn;
    }

    // ---- epilogue: masked sum-exp + gold capture ----
    #pragma unroll
    for (int mt = 0; mt < 4; mt++) {
        #pragma unroll
        for (int rh = 0; rh < 2; rh++) {
            int row = warpM * 64 + mt * 16 + rh * 8 + (lane >> 2);
            int labr = labsm[row];
            float se = 0.f;
            #pragma unroll
            for (int nt = 0; nt < 4; nt++) {
                int c0 = n0 + warpN * 32 + nt * 8 + (lane & 3) * 2;
                float v0 = acc[mt][nt][rh * 2 + 0];
                float v1 = acc[mt][nt][rh * 2 + 1];
                if (c0     < CCLS) se += __expf(v0);
                if (c0 + 1 < CCLS) se += __expf(v1);
                if (c0     == labr) g_gold[row0 + row] = v0;
                if (c0 + 1 == labr) g_gold[row0 + row] = v1;
            }
            se += __shfl_xor_sync(0xffffffffu, se, 1);
            se += __shfl_xor_sync(0xffffffffu, se, 2);
            if ((lane & 3) == 0) partial[row * 4 + warpN] = se;
        }
    }
    __syncthreads();
    if (tid < 128) {
        float t = partial[tid * 4] + partial[tid * 4 + 1]
                + partial[tid * 4 + 2] + partial[tid * 4 + 3];
        atomicAdd(&g_rowsum[row0 + tid], t);
    }
}

// ---------------------------------------------------------------------------
__global__ __launch_bounds__(256) void finalize(float* __restrict__ out) {
    int r = blockIdx.x * 256 + threadIdx.x;
    float loss = __logf(g_rowsum[r]) - g_gold[r];
    #pragma unroll
    for (int o = 16; o; o >>= 1) loss += __shfl_xor_sync(0xffffffffu, loss, o);
    __shared__ float ws[8];
    int w = threadIdx.x >> 5, l = threadIdx.x & 31;
    if (l == 0) ws[w] = loss;
    __syncthreads();
    if (threadIdx.x == 0) {
        float tot = 0.f;
        #pragma unroll
        for (int i = 0; i < 8; i++) tot += ws[i];
        atomicAdd(out, tot * (1.0f / (float)B_ROWS));
    }
}

// ---------------------------------------------------------------------------
extern "C" void kernel_launch(void* const* d_in, const int* in_sizes, int n_in,
                              void* d_out, int out_size) {
    const float*     hs = (const float*)d_in[0];
    const float*     pm = (const float*)d_in[1];
    const long long* lb = (const long long*)d_in[2];
    float* out = (float*)d_out;

    cudaFuncSetAttribute(gemm_ce, cudaFuncAttributeMaxDynamicSharedMemorySize, SMEM_TOTAL);

    prep_kernel<<<B_ROWS / 4 + 256, 256>>>(hs, pm, out);
    dim3 grid(B_ROWS / BM, 8);
    gemm_ce<<<grid, 256, SMEM_TOTAL>>>(lb);
    finalize<<<B_ROWS / 256, 256>>>(out);
}